// round 13
// baseline (speedup 1.0000x reference)
#include <cuda_runtime.h>
#include <math.h>

#define BB   8
#define HH   256
#define WW   256
#define HW   (HH*WW)
#define RPB  2
#define NBLK (BB*HH/RPB)          // 1024 blocks for horiz kernel

// Scratch (no device allocations allowed).
__device__ float2   g_dv[BB*HW];  // vertical EDT^2 per pixel (pos,neg) — 4MB, L2-resident
__device__ float    g_pp[NBLK];
__device__ float    g_pw[NBLK];
__device__ float    g_pc[NBLK];
__device__ unsigned g_ticket;     // zero-init; last block resets to 0

// ---------------------------------------------------------------------------
// Kernel V: vertical EDT via per-column register bitmasks.
// grid = 64 (image b, 32-column stripe k). 8 warps = 8 row-groups of 32 rows.
// Lane l owns column 32k+l; builds its 32-row group word with coalesced loads
// (bit j = targets[32g+j][col]). Window of +-32 rows via u64 concats of
// adjacent group words (smem-shared); nearest-1/0 via clz/ffs. Borders are
// zero-padded (nonexistent rows contribute no 1s and no 0s) — exact.
// Unresolved beyond +-32 (needs 65 identical rows, P~2^-32/px): exact serial
// gmem tail from r=33 (clamped reads; clamp re-asserts facts at <= radius).
// ---------------------------------------------------------------------------
__global__ void __launch_bounds__(256) vert_kernel(const int* __restrict__ targets) {
    int blk = blockIdx.x;         // b*8 + stripe
    int b   = blk >> 3;
    int k   = blk & 7;
    int g   = threadIdx.x >> 5;   // row group 0..7
    int l   = threadIdx.x & 31;
    int col = (k << 5) + l;

    // build this group's column word (coalesced: lanes read consecutive cols)
    const int* p = targets + b * HW + (g << 5) * WW + col;
    unsigned cw = 0;
#pragma unroll
    for (int j = 0; j < 32; j++) { cw |= ((unsigned)(*p)) << j; p += WW; }

    __shared__ unsigned scol[8][32];
    scol[g][l] = cw;
    __syncthreads();

    unsigned prev1 = (g > 0) ?  scol[g - 1][l] : 0u;
    unsigned next1 = (g < 7) ?  scol[g + 1][l] : 0u;
    unsigned cw0   = ~cw;
    unsigned prev0 = (g > 0) ? ~scol[g - 1][l] : 0u;   // border: no rows -> no 0s
    unsigned next0 = (g < 7) ? ~scol[g + 1][l] : 0u;

    // bit (32+j) of catA = row Rbase+j ; bit j = row Rbase-32+j
    unsigned long long catA1 = (unsigned long long)prev1 | ((unsigned long long)cw  << 32);
    unsigned long long catB1 = (unsigned long long)cw    | ((unsigned long long)next1 << 32);
    unsigned long long catA0 = (unsigned long long)prev0 | ((unsigned long long)cw0 << 32);
    unsigned long long catB0 = (unsigned long long)cw0   | ((unsigned long long)next0 << 32);

    int Rbase = g << 5;
    float2* outp = g_dv + b * HW + Rbase * WW + col;

#pragma unroll 8
    for (int i = 0; i < 32; i++) {
        int me = (int)((cw >> i) & 1u);

        // A: rows R-32..R-1 (bit31 = R-1, dist = clz+1); B: rows R+1..R+32 (dist = ffs)
        unsigned A1 = (unsigned)(catA1 >> i);
        unsigned B1 = (unsigned)(catB1 >> (i + 1));
        unsigned A0 = (unsigned)(catA0 >> i);
        unsigned B0 = (unsigned)(catB0 >> (i + 1));

        int r1, r0;
        if (me) r1 = 0;
        else {
            int da = A1 ? (__clz((int)A1) + 1) : 1000;
            int db = B1 ? __ffs((int)B1)       : 1000;
            r1 = min(da, db);
        }
        if (!me) r0 = 0;
        else {
            int da = A0 ? (__clz((int)A0) + 1) : 1000;
            int db = B0 ? __ffs((int)B0)       : 1000;
            r0 = min(da, db);
        }

        if (r1 >= 1000 || r0 >= 1000) {        // essentially-never exact tail
            int R = Rbase + i;
            const int* tc = targets + b * HW + col;
#pragma unroll 1
            for (int r = 33; r < HH; r++) {
                if (r1 < 1000 && r0 < 1000) break;
                int tu = tc[max(R - r, 0) * WW];
                int td = tc[min(R + r, HH - 1) * WW];
                if (r1 >= 1000 && (tu | td))      r1 = r;
                if (r0 >= 1000 && (tu & td) == 0) r0 = r;
            }
        }

        float d2p = (r1 <= 255) ? (float)(r1 * r1) : 1e9f;
        float d2n = (r0 <= 255) ? (float)(r0 * r0) : 1e9f;
        *outp = make_float2(d2p, d2n);         // coalesced across lanes
        outp += WW;
    }
}

// ---------------------------------------------------------------------------
// Kernel H: horizontal envelope + loss + reduction (R11's proven structure,
// vertical work removed; gt bit recovered as d2p==0).
// ---------------------------------------------------------------------------
__global__ void __launch_bounds__(256) horiz_kernel(
    const float* __restrict__ logits, float* __restrict__ out) {
    int blk = blockIdx.x;          // 0..1023
    int b   = blk >> 7;
    int h0  = (blk & 127) * RPB;
    int w   = threadIdx.x;

    // prologue: issue all gmem loads together
    float l0_[RPB], l1_[RPB];
    float2 v_[RPB];
#pragma unroll
    for (int i = 0; i < RPB; i++) {
        l0_[i] = logits[((b * 2 + 0) * HH + (h0 + i)) * WW + w];
        l1_[i] = logits[((b * 2 + 1) * HH + (h0 + i)) * WW + w];
        v_[i]  = g_dv[b * HW + (h0 + i) * WW + w];
    }

    __shared__ float2 srow[RPB][WW + 16];      // +-8 BIG pads
    if (w < 8) {
#pragma unroll
        for (int i = 0; i < RPB; i++) {
            srow[i][w]          = make_float2(1e9f, 1e9f);
            srow[i][WW + 8 + w] = make_float2(1e9f, 1e9f);
        }
    }
#pragma unroll
    for (int i = 0; i < RPB; i++) srow[i][8 + w] = v_[i];
    __syncthreads();

    float pred_[RPB];
#pragma unroll
    for (int i = 0; i < RPB; i++)
        pred_[i] = __fdividef(1.0f, 1.0f + __expf(l0_[i] - l1_[i]));

    float accP = 0.f, accW = 0.f;

#pragma unroll
    for (int i = 0; i < RPB; i++) {
        const float2* c = &srow[i][8 + w];
        float bp = v_[i].x, bn = v_[i].y;

        float2 L1 = c[-1], R1 = c[1];
        float2 L2 = c[-2], R2 = c[2];
        float2 L3 = c[-3], R3 = c[3];
        float2 L4 = c[-4], R4 = c[4];
        bp = fminf(bp, fminf(L1.x, R1.x) + 1.0f);  bn = fminf(bn, fminf(L1.y, R1.y) + 1.0f);
        bp = fminf(bp, fminf(L2.x, R2.x) + 4.0f);  bn = fminf(bn, fminf(L2.y, R2.y) + 4.0f);
        bp = fminf(bp, fminf(L3.x, R3.x) + 9.0f);  bn = fminf(bn, fminf(L3.y, R3.y) + 9.0f);
        bp = fminf(bp, fminf(L4.x, R4.x) + 16.0f); bn = fminf(bn, fminf(L4.y, R4.y) + 16.0f);

        if (fmaxf(bp, bn) > 25.0f) {
            float2 L5 = c[-5], R5 = c[5];
            float2 L6 = c[-6], R6 = c[6];
            float2 L7 = c[-7], R7 = c[7];
            float2 L8 = c[-8], R8 = c[8];
            bp = fminf(bp, fminf(L5.x, R5.x) + 25.0f); bn = fminf(bn, fminf(L5.y, R5.y) + 25.0f);
            bp = fminf(bp, fminf(L6.x, R6.x) + 36.0f); bn = fminf(bn, fminf(L6.y, R6.y) + 36.0f);
            bp = fminf(bp, fminf(L7.x, R7.x) + 49.0f); bn = fminf(bn, fminf(L7.y, R7.y) + 49.0f);
            bp = fminf(bp, fminf(L8.x, R8.x) + 64.0f); bn = fminf(bn, fminf(L8.y, R8.y) + 64.0f);

            if (fmaxf(bp, bn) > 81.0f) {       // rare exact serial tail
#pragma unroll 1
                for (int r = 9; r < WW; r++) {
                    float rr = (float)(r * r);
                    if (rr >= bp && rr >= bn) break;
                    if (w - r >= 0) {
                        float2 a = srow[i][8 + w - r];
                        bp = fminf(bp, a.x + rr); bn = fminf(bn, a.y + rr);
                    }
                    if (w + r < WW) {
                        float2 d = srow[i][8 + w + r];
                        bp = fminf(bp, d.x + rr); bn = fminf(bn, d.y + rr);
                    }
                }
            }
        }

        accP += pred_[i];
        accW += pred_[i] * (sqrtf(bp) - sqrtf(bn));
    }

    // ---- counts via ballots (gt <=> vertical d2p == 0) ----
    unsigned m = 0xFFFFFFFFu;
    int wcnt = 0;
#pragma unroll
    for (int i = 0; i < RPB; i++)
        wcnt += __popc(__ballot_sync(m, v_[i].x == 0.0f));
    float cv = (float)wcnt;

    // ---- deterministic block reduction ----
#pragma unroll
    for (int o = 16; o > 0; o >>= 1) {
        accP += __shfl_down_sync(m, accP, o);
        accW += __shfl_down_sync(m, accW, o);
    }
    __shared__ float rr0[8], rr1[8], rr2[8];
    if ((w & 31) == 0) {
        rr0[w >> 5] = accP; rr1[w >> 5] = accW; rr2[w >> 5] = cv;
    }
    __syncthreads();

    __shared__ bool s_last;
    if (w == 0) {
        float s0 = 0.f, s1 = 0.f, s2 = 0.f;
#pragma unroll
        for (int i = 0; i < 8; i++) { s0 += rr0[i]; s1 += rr1[i]; s2 += rr2[i]; }
        g_pp[blk] = s0;
        g_pw[blk] = s1;
        g_pc[blk] = s2;
        __threadfence();
        unsigned tk = atomicAdd(&g_ticket, 1u);
        s_last = (tk == (unsigned)(NBLK - 1));
    }
    __syncthreads();
    if (!s_last) return;

    // ---- last block: global reduction (deterministic order) ----
    int wb   = w >> 5;
    int lane = w & 31;
    int base = wb * 128;
    float s0 = 0.f, s1 = 0.f, s2 = 0.f;
#pragma unroll
    for (int i = 0; i < 4; i++) {
        int idx = base + lane + i * 32;
        s0 += __ldcg(&g_pp[idx]);
        s1 += __ldcg(&g_pw[idx]);
        s2 += __ldcg(&g_pc[idx]);
    }
#pragma unroll
    for (int o = 16; o > 0; o >>= 1) {
        s0 += __shfl_down_sync(m, s0, o);
        s1 += __shfl_down_sync(m, s1, o);
        s2 += __shfl_down_sync(m, s2, o);
    }
    __shared__ float pb[8];
    if (lane == 0) {
        float inv = 1.0f / (float)HW;
        float mean_pred = s0 * inv;
        float mean_w    = s1 * inv;
        float per_b;
        if (s2 == 0.0f)           per_b = mean_pred;
        else if (s2 == (float)HW) per_b = 1.0f - mean_pred;
        else                      per_b = mean_w;
        pb[wb] = per_b;
    }
    __syncthreads();
    if (w == 0) {
        float total = 0.f;
#pragma unroll
        for (int i = 0; i < BB; i++) total += pb[i];
        out[0] = total / (float)BB;
        g_ticket = 0;                          // reset for next graph replay
    }
}

extern "C" void kernel_launch(void* const* d_in, const int* in_sizes, int n_in,
                              void* d_out, int out_size) {
    const float* logits  = (const float*)d_in[0];
    const int*   targets = (const int*)d_in[1];
    float*       out     = (float*)d_out;

    vert_kernel<<<64, 256>>>(targets);
    horiz_kernel<<<NBLK, 256>>>(logits, out);
}